// round 7
// baseline (speedup 1.0000x reference)
#include <cuda_runtime.h>
#include <cuda_fp16.h>
#include <math.h>

#define BATCH   16
#define NPTS    256
#define FDIM    64
#define FPRIME  16
#define HDIM    128
#define TLUT    256
#define DMAX    1.7321f
#define ITILE   16
#define S1_THREADS 256
#define MLP_THREADS 256

// nearest-neighbor LUT, full f: u32[t*32+p] = half2(v_{2p}, v_{2p+1}) at d = t*h
__device__ uint4 g_lutRaw[TLUT * 8];
// f_bar staging between stage-1 and the pointwise MLP
__device__ float g_fbar[BATCH * NPTS * FDIM];

__device__ __forceinline__ float sp(float x) {
    return fmaxf(x, 0.0f) + log1pf(expf(-fabsf(x)));
}

// ---------------------------------------------------------------------------
// LUT build: 32 blocks x 8 knots x 256 threads.
// ---------------------------------------------------------------------------
__global__ __launch_bounds__(256)
void build_lut_kernel(const float* __restrict__ mp_w1,
                      const float* __restrict__ mp_b1,
                      const float* __restrict__ mp_w2,
                      const float* __restrict__ mp_b2) {
    __shared__ float w2s[HDIM * FDIM];
    __shared__ float hid[8][HDIM];
    __shared__ float v[8][FDIM];
    const int blk = blockIdx.x, tid = threadIdx.x;
    const float hstep = DMAX / (float)TLUT;

    const float4* w2v = (const float4*)mp_w2;
    float4* w2sv = (float4*)w2s;
    #pragma unroll
    for (int k = tid; k < HDIM * FDIM / 4; k += 256) w2sv[k] = w2v[k];
    #pragma unroll
    for (int k = tid; k < 8 * HDIM; k += 256) {
        int e = k >> 7, hh = k & 127;
        float d = (float)(blk * 8 + e) * hstep;
        hid[e][hh] = sp(fmaf(d, mp_w1[hh], mp_b1[hh]));
    }
    __syncthreads();
    {
        int e = tid >> 6, ff = tid & 63;           // e in 0..3 -> knots e, e+4
        float a0 = mp_b2[ff], a1 = a0;
        #pragma unroll 8
        for (int k = 0; k < HDIM; k++) {
            float w = w2s[k * FDIM + ff];
            a0 = fmaf(hid[e][k],     w, a0);
            a1 = fmaf(hid[e + 4][k], w, a1);
        }
        v[e][ff]     = sp(a0);
        v[e + 4][ff] = sp(a1);
    }
    __syncthreads();
    {
        int e = tid >> 5, p = tid & 31;
        __half2 vh = __floats2half2_rn(v[e][2 * p], v[e][2 * p + 1]);
        ((unsigned int*)g_lutRaw)[(blk * 8 + e) * 32 + p] =
            *reinterpret_cast<unsigned int*>(&vh);
    }
}

// ---------------------------------------------------------------------------
// Stage-1 kernel: CTA = (i-tile 16, batch, f-half 32f). 256 threads, 5 CTAs/SM.
// SMEM (45056 B dynamic):
//   [0,    16384)  lutS  fp16 LUT half  [t*16 + q]
//   [16384,32768)  fbS   f-half tile    [j*16 + q]  (half2)
//   [32768,40960)  tS    u16 byte-offset (it<<6), layout [j*16 + i]
//   [40960,45056)  rS    float4 positions
// partS overlays [0, ~20.5K) after stage-1, stride 20 u32 per (i,fq) row.
// Half-warp h processes j = 2m+h within the warp's 32-j strip; lane's f-pair fq.
// ---------------------------------------------------------------------------
__global__ __launch_bounds__(S1_THREADS, 5)
void stage1_kernel(const float* __restrict__ r, const float* __restrict__ f) {
    extern __shared__ char smem[];
    unsigned int*   lutS  = (unsigned int*)smem;
    unsigned int*   fbS   = (unsigned int*)(smem + 16384);
    unsigned short* tS    = (unsigned short*)(smem + 32768);
    float4*         rS    = (float4*)(smem + 40960);
    unsigned int*   partS = (unsigned int*)smem;

    const int hf   = blockIdx.z;
    const int b    = blockIdx.y;
    const int i0   = blockIdx.x * ITILE;
    const int tid  = threadIdx.x;
    const int w    = tid >> 5;
    const int lane = tid & 31;
    const int fq   = lane & 15;
    const int h    = lane >> 4;

    // ---- tile loads ----
    uint4* lutSv = (uint4*)lutS;
    #pragma unroll
    for (int k = tid; k < TLUT * 4; k += S1_THREADS) {
        int t = k >> 2, qg = k & 3;
        lutSv[k] = g_lutRaw[t * 8 + hf * 4 + qg];
    }
    const float4* fbG = (const float4*)(f + ((size_t)b * NPTS) * FDIM + hf * 32);
    #pragma unroll
    for (int k = tid; k < NPTS * 8; k += S1_THREADS) {
        int j = k >> 3, g = k & 7;
        float4 v = fbG[j * 16 + g];               // row stride 64 floats = 16 float4
        __half2 h0 = __floats2half2_rn(v.x, v.y);
        __half2 h1 = __floats2half2_rn(v.z, v.w);
        fbS[j * 16 + g * 2]     = *reinterpret_cast<unsigned int*>(&h0);
        fbS[j * 16 + g * 2 + 1] = *reinterpret_cast<unsigned int*>(&h1);
    }
    const float* rG = r + (size_t)b * NPTS * 3;
    if (tid < NPTS)
        rS[tid] = make_float4(rG[3 * tid], rG[3 * tid + 1], rG[3 * tid + 2], 0.0f);
    __syncthreads();

    // ---- stage A: nearest-knot byte offsets (redundant across f-halves) ----
    const float scale = (float)TLUT / DMAX;
    #pragma unroll
    for (int k = 0; k < (ITILE * NPTS) / S1_THREADS; k++) {
        int idx = tid + k * S1_THREADS;
        int jj = idx >> 4, ii = idx & 15;
        float4 ri = rS[i0 + ii], rj = rS[jj];
        float dx = ri.x - rj.x, dy = ri.y - rj.y, dz = ri.z - rj.z;
        float d  = sqrtf(fmaf(dx, dx, fmaf(dy, dy, dz * dz)));
        int it = (int)(fmaf(d, scale, 0.5f));
        it = min(it, TLUT - 1);
        tS[jj * 16 + ii] = (unsigned short)(it << 6);  // byte off = it * 16 * 4
    }
    __syncthreads();

    // ---- stage 1: warp w covers j in [32w, 32w+32); half-warp h takes 2m+h ----
    const char* lutLane = smem + (size_t)fq * 4;
    const char* tPtr    = smem + 32768 + (size_t)(w * 32 + h) * 32;
    const char* fbPtr   = smem + 16384 + (size_t)(w * 32 + h) * 64 + fq * 4;

    __half2 acc[16];
    #pragma unroll
    for (int ii = 0; ii < 16; ii++) acc[ii] = __float2half2_rn(0.0f);

    #pragma unroll
    for (int m = 0; m < 16; m++) {
        uint4 q0 = *(const uint4*)(tPtr + m * 64);        // offsets i0..7 (this j)
        uint4 q1 = *(const uint4*)(tPtr + m * 64 + 16);   // offsets i8..15
        unsigned int fbits = *(const unsigned int*)(fbPtr + m * 128);
        __half2 fb2 = *reinterpret_cast<__half2*>(&fbits);
        unsigned int qq[8] = {q0.x, q0.y, q0.z, q0.w, q1.x, q1.y, q1.z, q1.w};
        #pragma unroll
        for (int p = 0; p < 8; p++) {
            unsigned int olo = qq[p] & 0xFFFFu;
            unsigned int ohi = qq[p] >> 16;
            __half2 L0 = *(const __half2*)(lutLane + olo);
            __half2 L1 = *(const __half2*)(lutLane + ohi);
            acc[2 * p]     = __hfma2(L0, fb2, acc[2 * p]);
            acc[2 * p + 1] = __hfma2(L1, fb2, acc[2 * p + 1]);
        }
    }
    __syncthreads();   // lutS/fbS reads done

    // ---- partials: slot = w*2+h, row (ii,fq) stride 20 (16B-aligned, 2-way bc) ----
    #pragma unroll
    for (int ii = 0; ii < 16; ii++)
        partS[(ii * 16 + fq) * 20 + (w * 2 + h)] =
            *reinterpret_cast<unsigned int*>(&acc[ii]);
    __syncthreads();

    // ---- reduce 16 partials in fp32; softplus; write f_bar ----
    {
        int ii = tid >> 4, q = tid & 15;
        const uint4* pr = (const uint4*)(partS + (ii * 16 + q) * 20);
        float sx = 0.0f, sy = 0.0f;
        #pragma unroll
        for (int g = 0; g < 4; g++) {
            uint4 u = pr[g];
            unsigned int uu[4] = {u.x, u.y, u.z, u.w};
            #pragma unroll
            for (int e = 0; e < 4; e++) {
                float2 pv = __half22float2(*reinterpret_cast<__half2*>(&uu[e]));
                sx += pv.x; sy += pv.y;
            }
        }
        float2 o;
        o.x = sp(sx);
        o.y = sp(sy);
        *(float2*)(g_fbar + ((size_t)b * NPTS + i0 + ii) * FDIM + hf * 32 + q * 2) = o;
    }
}

// ---------------------------------------------------------------------------
// MLP kernel: 128 CTAs x 32 rows. f_bar -> sp(f_bar@w1+b1) -> sp(@w2+b2).
// SMEM (66880 B): w1 32K | w2T 8448 (stride 132) | fbar 8K | h2 16896 | biases
// ---------------------------------------------------------------------------
__global__ __launch_bounds__(MLP_THREADS)
void mlp_kernel(const float* __restrict__ pc_w1, const float* __restrict__ pc_b1,
                const float* __restrict__ pc_w2, const float* __restrict__ pc_b2,
                float* __restrict__ out) {
    extern __shared__ char smem[];
    float* w1S   = (float*)smem;                 // 64*128
    float* w2T   = (float*)(smem + 32768);       // 16 p * stride 132
    float* fbarS = (float*)(smem + 41216);       // 32*64
    float* h2S   = (float*)(smem + 49408);       // 32 * stride 132
    float* b1S   = (float*)(smem + 66304);
    float* b2S   = (float*)(smem + 66816);

    const int row0 = blockIdx.x * 32;
    const int tid = threadIdx.x, w = tid >> 5, lane = tid & 31;

    const float4* w1v = (const float4*)pc_w1;
    float4* w1Sv = (float4*)w1S;
    #pragma unroll
    for (int k = tid; k < HDIM * FDIM / 4; k += MLP_THREADS) w1Sv[k] = w1v[k];
    #pragma unroll
    for (int k = tid; k < HDIM * FPRIME; k += MLP_THREADS) {
        int hh = k >> 4, p = k & 15;
        w2T[p * 132 + hh] = pc_w2[k];
    }
    const float4* fbv = (const float4*)(g_fbar + (size_t)row0 * FDIM);
    float4* fbSv = (float4*)fbarS;
    #pragma unroll
    for (int k = tid; k < 32 * FDIM / 4; k += MLP_THREADS) fbSv[k] = fbv[k];
    if (tid < HDIM)   b1S[tid] = pc_b1[tid];
    if (tid < FPRIME) b2S[tid] = pc_b2[tid];
    __syncthreads();

    // layer 1: warp w rows 4w..4w+3; lane owns h-cols lane+32k
    {
        float acc[4][4];
        #pragma unroll
        for (int kk = 0; kk < 4; kk++) {
            float bv = b1S[lane + 32 * kk];
            #pragma unroll
            for (int rr = 0; rr < 4; rr++) acc[rr][kk] = bv;
        }
        #pragma unroll 4
        for (int ff = 0; ff < FDIM; ff++) {
            float w1r[4];
            #pragma unroll
            for (int kk = 0; kk < 4; kk++) w1r[kk] = w1S[ff * HDIM + lane + 32 * kk];
            #pragma unroll
            for (int rr = 0; rr < 4; rr++) {
                float fv = fbarS[(4 * w + rr) * FDIM + ff];
                #pragma unroll
                for (int kk = 0; kk < 4; kk++)
                    acc[rr][kk] = fmaf(fv, w1r[kk], acc[rr][kk]);
            }
        }
        #pragma unroll
        for (int rr = 0; rr < 4; rr++)
            #pragma unroll
            for (int kk = 0; kk < 4; kk++)
                h2S[(4 * w + rr) * 132 + lane + 32 * kk] = sp(acc[rr][kk]);
    }
    __syncthreads();

    // layer 2: 512 (row, p) pairs over 256 threads
    #pragma unroll
    for (int it2 = 0; it2 < 2; it2++) {
        int idx = tid + it2 * MLP_THREADS;
        int i = idx >> 4, p = idx & 15;
        float o = b2S[p];
        const float4* hv4 = (const float4*)(h2S + i * 132);
        const float4* wv4 = (const float4*)(w2T + p * 132);
        #pragma unroll 8
        for (int hh = 0; hh < HDIM / 4; hh++) {
            float4 hv = hv4[hh], wv = wv4[hh];
            o = fmaf(hv.x, wv.x, o);
            o = fmaf(hv.y, wv.y, o);
            o = fmaf(hv.z, wv.z, o);
            o = fmaf(hv.w, wv.w, o);
        }
        out[(size_t)(row0 + i) * FPRIME + p] = sp(o);
    }
}

// ---------------------------------------------------------------------------
extern "C" void kernel_launch(void* const* d_in, const int* in_sizes, int n_in,
                              void* d_out, int out_size) {
    const float* r     = (const float*)d_in[0];
    const float* f     = (const float*)d_in[1];
    const float* mp_w1 = (const float*)d_in[2];
    const float* mp_b1 = (const float*)d_in[3];
    const float* mp_w2 = (const float*)d_in[4];
    const float* mp_b2 = (const float*)d_in[5];
    const float* pc_w1 = (const float*)d_in[6];
    const float* pc_b1 = (const float*)d_in[7];
    const float* pc_w2 = (const float*)d_in[8];
    const float* pc_b2 = (const float*)d_in[9];
    float* out = (float*)d_out;

    cudaFuncSetAttribute(mlp_kernel,
                         cudaFuncAttributeMaxDynamicSharedMemorySize, 66880);

    build_lut_kernel<<<TLUT / 8, 256>>>(mp_w1, mp_b1, mp_w2, mp_b2);

    dim3 g1(NPTS / ITILE, BATCH, 2);
    stage1_kernel<<<g1, S1_THREADS, 45056>>>(r, f);

    mlp_kernel<<<(BATCH * NPTS) / 32, MLP_THREADS, 66880>>>(
        pc_w1, pc_b1, pc_w2, pc_b2, out);
}

// round 8
// speedup vs baseline: 1.0600x; 1.0600x over previous
#include <cuda_runtime.h>
#include <cuda_fp16.h>
#include <math.h>

#define BATCH   16
#define NPTS    256
#define FDIM    64
#define FPRIME  16
#define HDIM    128
#define TLUT    256
#define DMAX    1.7321f
#define ITILE   16
#define THREADS 512

// nearest-neighbor LUT: row t = 64 halves (128 B), g_f(t * DMAX/TLUT)
__device__ __half g_lutHalf[TLUT * FDIM];

__device__ __forceinline__ float sp(float x) {
    return fmaxf(x, 0.0f) + log1pf(expf(-fabsf(x)));
}
__device__ __forceinline__ __half2 u2h(unsigned int u) {
    return *reinterpret_cast<__half2*>(&u);
}

// ---------------------------------------------------------------------------
// LUT build: 256 blocks (1 knot) x 64 threads (1 f each). w2 from L2 directly.
// ---------------------------------------------------------------------------
__global__ __launch_bounds__(64)
void build_lut_kernel(const float* __restrict__ mp_w1,
                      const float* __restrict__ mp_b1,
                      const float* __restrict__ mp_w2,
                      const float* __restrict__ mp_b2) {
    __shared__ float hid[HDIM];
    const int t = blockIdx.x, tid = threadIdx.x;
    const float d = (float)t * (DMAX / (float)TLUT);
    hid[tid]      = sp(fmaf(d, mp_w1[tid],      mp_b1[tid]));
    hid[tid + 64] = sp(fmaf(d, mp_w1[tid + 64], mp_b1[tid + 64]));
    __syncthreads();
    float a = mp_b2[tid];
    #pragma unroll 8
    for (int h = 0; h < HDIM; h++)
        a = fmaf(hid[h], __ldg(mp_w2 + h * FDIM + tid), a);
    g_lutHalf[t * FDIM + tid] = __float2half_rn(sp(a));
}

// ---------------------------------------------------------------------------
// Main fused kernel. CTA = (16-i tile, batch). 512 threads, 2 CTAs/SM, 1 wave.
// SMEM (77824 B):
//   [0,    32768)  lutS  LUT rows, 128 B per knot (uint4-gatherable)
//   [32768,65536)  fbS   f tile, 128 B per j (64 halves)
//   [65536,73728)  tS    u16 byte-offset (it<<7), layout [j][i]
//   [73728,77824)  rS    float4 positions
// Overlays (after stage-1 sync):
//   partS @0      (16 i * 4 strip * 64 f fp32 = 16384)
//   fbarS @16384  (16*64 fp32 = 4096)
//   h2S   @20480  (16 * 132 fp32 = 8448)
//   w1S   @32768  (64*128 fp32 = 32768)      over fbS
//   w2T   @65536  (16 p * 132 fp32 = 8448)   over tS (+256B of rS)
//   b1S   @74240, b2S @74752                 over rS
// Warp w: i-group ig=w&3 (4 i via quarter-warps), j-strip s=w>>2 (64 j).
// Lane: qw=lane>>3 selects i, q=lane&7 covers f = 8q..8q+7 (16 B).
// ---------------------------------------------------------------------------
__global__ __launch_bounds__(THREADS, 2)
void property_predictor_main(const float* __restrict__ r,
                             const float* __restrict__ f,
                             const float* __restrict__ pc_w1,
                             const float* __restrict__ pc_b1,
                             const float* __restrict__ pc_w2,
                             const float* __restrict__ pc_b2,
                             float* __restrict__ out) {
    extern __shared__ char smem[];
    float4* rS    = (float4*)(smem + 73728);
    float*  partS = (float*)smem;
    float*  fbarS = (float*)(smem + 16384);
    float*  h2S   = (float*)(smem + 20480);
    float*  w1S   = (float*)(smem + 32768);
    float*  w2T   = (float*)(smem + 65536);
    float*  b1S   = (float*)(smem + 74240);
    float*  b2S   = (float*)(smem + 74752);

    const int b    = blockIdx.y;
    const int i0   = blockIdx.x * ITILE;
    const int tid  = threadIdx.x;
    const int w    = tid >> 5;
    const int lane = tid & 31;
    const int qw   = lane >> 3;     // quarter-warp id -> local i
    const int q    = lane & 7;      // 16B f-slice within row

    // ---- tile loads ----
    {
        const uint4* lutG = (const uint4*)g_lutHalf;
        uint4* lutSv = (uint4*)smem;
        #pragma unroll
        for (int k = tid; k < TLUT * 8; k += THREADS) lutSv[k] = lutG[k];
    }
    {
        const float4* fbG = (const float4*)(f + (size_t)b * NPTS * FDIM);
        uint2* fbSv = (uint2*)(smem + 32768);
        #pragma unroll
        for (int k = tid; k < NPTS * 16; k += THREADS) {
            float4 v = fbG[k];
            __half2 h0 = __floats2half2_rn(v.x, v.y);
            __half2 h1 = __floats2half2_rn(v.z, v.w);
            uint2 e;
            e.x = *reinterpret_cast<unsigned int*>(&h0);
            e.y = *reinterpret_cast<unsigned int*>(&h1);
            fbSv[k] = e;
        }
    }
    {
        const float* rG = r + (size_t)b * NPTS * 3;
        for (int k = tid; k < NPTS; k += THREADS)
            rS[k] = make_float4(rG[3 * k], rG[3 * k + 1], rG[3 * k + 2], 0.0f);
    }
    __syncthreads();

    // ---- stage A: nearest-knot byte offsets tS[j*16+i] = it*128 ----
    const float scale = (float)TLUT / DMAX;
    #pragma unroll
    for (int k = 0; k < (ITILE * NPTS) / THREADS; k++) {
        int idx = tid + k * THREADS;
        int jj = idx >> 4, ii = idx & 15;
        float4 ri = rS[i0 + ii], rj = rS[jj];
        float dx = ri.x - rj.x, dy = ri.y - rj.y, dz = ri.z - rj.z;
        float d  = sqrtf(fmaf(dx, dx, fmaf(dy, dy, dz * dz)));
        int it = (int)(fmaf(d, scale, 0.5f));
        it = min(it, TLUT - 1);
        *(unsigned short*)(smem + 65536 + jj * 32 + ii * 2) =
            (unsigned short)(it << 7);
    }
    __syncthreads();

    // ---- stage 1: quad-gather. warp = 4 i x 64 j ----
    const int ig = w & 3;           // i-group: i = ig*4 + qw
    const int s  = w >> 2;          // j-strip: j in [64s, 64s+64)
    const char* lutq = smem + (q << 4);
    const char* fbp  = smem + 32768 + (size_t)(s * 64) * 128 + (q << 4);
    const char* top  = smem + 65536 + (size_t)(s * 64) * 32 + ((ig * 4 + qw) << 1);

    float facc[8];
    #pragma unroll
    for (int e = 0; e < 8; e++) facc[e] = 0.0f;

    #pragma unroll
    for (int c = 0; c < 4; c++) {              // 4 chunks of 16 j
        __half2 a0 = __float2half2_rn(0.0f), a1 = a0, a2 = a0, a3 = a0;
        #pragma unroll
        for (int jj = 0; jj < 16; jj++) {
            unsigned int off = *(const unsigned short*)top;  top += 32;
            uint4 L  = *(const uint4*)(lutq + off);
            uint4 Fv = *(const uint4*)fbp;                   fbp += 128;
            a0 = __hfma2(u2h(L.x), u2h(Fv.x), a0);
            a1 = __hfma2(u2h(L.y), u2h(Fv.y), a1);
            a2 = __hfma2(u2h(L.z), u2h(Fv.z), a2);
            a3 = __hfma2(u2h(L.w), u2h(Fv.w), a3);
        }
        float2 t0 = __half22float2(a0), t1 = __half22float2(a1);
        float2 t2 = __half22float2(a2), t3 = __half22float2(a3);
        facc[0] += t0.x; facc[1] += t0.y; facc[2] += t1.x; facc[3] += t1.y;
        facc[4] += t2.x; facc[5] += t2.y; facc[6] += t3.x; facc[7] += t3.y;
    }
    __syncthreads();   // all lutS/fbS/tS reads complete

    // ---- write fp32 partials; stage pointwise-MLP weights ----
    {
        int iloc = ig * 4 + qw;
        float4* pp = (float4*)(partS + ((iloc * 4 + s) * FDIM + q * 8));
        pp[0] = make_float4(facc[0], facc[1], facc[2], facc[3]);
        pp[1] = make_float4(facc[4], facc[5], facc[6], facc[7]);
    }
    {
        const float4* w1v = (const float4*)pc_w1;
        float4* w1Sv = (float4*)w1S;
        #pragma unroll
        for (int k = tid; k < FDIM * HDIM / 4; k += THREADS) w1Sv[k] = w1v[k];
        #pragma unroll
        for (int k = tid; k < HDIM * FPRIME; k += THREADS) {
            int hh = k >> 4, p = k & 15;
            w2T[p * 132 + hh] = pc_w2[k];
        }
        if (tid < HDIM)   b1S[tid] = pc_b1[tid];
        if (tid < FPRIME) b2S[tid] = pc_b2[tid];
    }
    __syncthreads();

    // ---- reduce 4 strips (fp32) + softplus -> fbarS ----
    #pragma unroll
    for (int k = 0; k < 2; k++) {
        int idx = tid + k * THREADS;           // 1024 (i,f) cells
        int ii = idx >> 6, ff = idx & 63;
        const float* pr = partS + ii * 4 * FDIM + ff;
        float sum = pr[0] + pr[FDIM] + pr[2 * FDIM] + pr[3 * FDIM];
        fbarS[ii * FDIM + ff] = sp(sum);
    }
    __syncthreads();

    // ---- stage 2 layer 1: warps 0..7, rows (2w, 2w+1); lane: 4 h-cols ----
    if (w < 8) {
        float a0[4], a1[4];
        #pragma unroll
        for (int kk = 0; kk < 4; kk++) { a0[kk] = b1S[lane + 32 * kk]; a1[kk] = a0[kk]; }
        #pragma unroll 8
        for (int ff = 0; ff < FDIM; ff++) {
            float f0 = fbarS[(2 * w) * FDIM + ff];
            float f1 = fbarS[(2 * w + 1) * FDIM + ff];
            #pragma unroll
            for (int kk = 0; kk < 4; kk++) {
                float wv = w1S[ff * HDIM + lane + 32 * kk];
                a0[kk] = fmaf(f0, wv, a0[kk]);
                a1[kk] = fmaf(f1, wv, a1[kk]);
            }
        }
        #pragma unroll
        for (int kk = 0; kk < 4; kk++) {
            h2S[(2 * w) * 132 + lane + 32 * kk]     = sp(a0[kk]);
            h2S[(2 * w + 1) * 132 + lane + 32 * kk] = sp(a1[kk]);
        }
    }
    __syncthreads();

    // ---- stage 2 layer 2: 256 threads = (row i, out-col p) ----
    if (tid < ITILE * FPRIME) {
        int i = tid >> 4, p = tid & 15;
        float o = b2S[p];
        const float4* hv4 = (const float4*)(h2S + i * 132);
        const float4* wv4 = (const float4*)(w2T + p * 132);
        #pragma unroll 8
        for (int hh = 0; hh < HDIM / 4; hh++) {
            float4 hv = hv4[hh], wv = wv4[hh];
            o = fmaf(hv.x, wv.x, o);
            o = fmaf(hv.y, wv.y, o);
            o = fmaf(hv.z, wv.z, o);
            o = fmaf(hv.w, wv.w, o);
        }
        out[((size_t)(b * NPTS + i0 + i)) * FPRIME + p] = sp(o);
    }
}

// ---------------------------------------------------------------------------
extern "C" void kernel_launch(void* const* d_in, const int* in_sizes, int n_in,
                              void* d_out, int out_size) {
    const float* r     = (const float*)d_in[0];
    const float* f     = (const float*)d_in[1];
    const float* mp_w1 = (const float*)d_in[2];
    const float* mp_b1 = (const float*)d_in[3];
    const float* mp_w2 = (const float*)d_in[4];
    const float* mp_b2 = (const float*)d_in[5];
    const float* pc_w1 = (const float*)d_in[6];
    const float* pc_b1 = (const float*)d_in[7];
    const float* pc_w2 = (const float*)d_in[8];
    const float* pc_b2 = (const float*)d_in[9];
    float* out = (float*)d_out;

    build_lut_kernel<<<TLUT, 64>>>(mp_w1, mp_b1, mp_w2, mp_b2);

    cudaFuncSetAttribute(property_predictor_main,
                         cudaFuncAttributeMaxDynamicSharedMemorySize, 77824);
    dim3 grid(NPTS / ITILE, BATCH);
    property_predictor_main<<<grid, THREADS, 77824>>>(
        r, f, pc_w1, pc_b1, pc_w2, pc_b2, out);
}